// round 15
// baseline (speedup 1.0000x reference)
#include <cuda_runtime.h>
#include <math.h>

// Problem constants
#define N1v 4000
#define N2v 4000
#define GD  8000
#define RD  20000
#define M1v 1200
#define M2v 1200
#define MGv 2400
#define MRv 6000

// Loss tiling: 2 j-columns per thread, 512-wide j-tiles -> 874 blocks (single wave)
#define GXJ 12            // ceil(MRv/512)
#define GY3 38            // ceil(MGv/64)
#define NB3 (GXJ*GY3)     // 456
#define GY2 19            // ceil(M2v/64)
#define NB2 (GXJ*GY2)     // 228
#define GX1 5             // ceil(MGv/512)
#define GY1 38            // ceil(M1v/32)
#define NB1 (GX1*GY1)     // 190
#define NBT (NB3+NB2+NB1) // 874

#define NPREP 11          // prep blocks (11*1024 = 11264 >= 10800)
#define NSP   (4+NPREP)   // fused sort+prep grid

// ---------------- device scratch (no allocation allowed) ----------------
__device__ int    d_s1[M1v], d_s2[M2v], d_sg[MGv], d_sr[MRv];
__device__ float  d_w1[M1v], d_w2[M2v], d_wg[MGv], d_wr[MRv];
__device__ float4 d_q1[M1v], d_q2[M2v], d_pg[MGv], d_pr[MRv];
__device__ int    d_nu[4];      // unique counts: [m1, m2, mg, mr]
// 0: loss1, 1: loss2, 2: S (trace), 3: ||Pg||^2, 4: ||Pr||^2
__device__ double d_acc[5];
__device__ int    d_sd, d_pd;   // sort-done / prep-done counters (self-resetting)

// ---------------- helpers ----------------
__device__ __forceinline__ void softmax3(float a, float b, float c,
                                         float& p0, float& p1, float& p2) {
    float m  = fmaxf(a, fmaxf(b, c));
    float e0 = __expf(a - m), e1 = __expf(b - m), e2 = __expf(c - m);
    float inv = 1.0f / (e0 + e1 + e2);
    p0 = e0 * inv; p1 = e1 * inv; p2 = e2 * inv;
}

__device__ __forceinline__ float warp_sum(float v) {
    #pragma unroll
    for (int off = 16; off > 0; off >>= 1)
        v += __shfl_down_sync(0xFFFFFFFFu, v, off);
    return v;
}

// ---------------- fused sort+prep: 4 sort blocks + 11 prep blocks ----------------
// Sort blocks (0-3) do the counting sort + dedup (exact: sums are permutation-
// invariant; duplicates -> multiplicity weights; sorted unique columns give
// quasi-coalesced gathers). Prep blocks (4-14) spin on the sort-done counter,
// then build the softmax/Q tables in parallel. All 15 blocks are co-resident
// (each SM fits one 1024-thread/80KB block; 15 << 148), so the spin is safe.
__global__ void sort_prep_kernel(
        const int* __restrict__ m1, const int* __restrict__ m2,
        const int* __restrict__ mg, const int* __restrict__ mr,
        const float* __restrict__ C1, const float* __restrict__ C2,
        const float* __restrict__ Cg, const float* __restrict__ Cr,
        const float* __restrict__ Ai, const float* __restrict__ bg,
        const float* __restrict__ br, const float* __restrict__ b1,
        const float* __restrict__ b2) {
    extern __shared__ int sh[];           // sort histogram (up to RD ints)
    __shared__ int wsum[32];
    __shared__ float red_a[32], red_b[32];
    const int b = blockIdx.x;
    const int tid = threadIdx.x, bd = blockDim.x;   // 1024
    const int lane = tid & 31, wid = tid >> 5;

    if (b < 4) {
        // ================= sort block =================
        const int* in; int n, vmax; int* outv; float* outw;
        if      (b == 0) { in = m1; n = M1v; vmax = N1v; outv = d_s1; outw = d_w1; }
        else if (b == 1) { in = m2; n = M2v; vmax = N2v; outv = d_s2; outw = d_w2; }
        else if (b == 2) { in = mg; n = MGv; vmax = GD;  outv = d_sg; outw = d_wg; }
        else             { in = mr; n = MRv; vmax = RD;  outv = d_sr; outw = d_wr; }

        if (b == 0 && tid < 5) d_acc[tid] = 0.0;   // reset accumulators each replay

        {   // zero histogram (int4; vmax % 4 == 0, extern smem 16B aligned)
            int4* s4 = reinterpret_cast<int4*>(sh);
            for (int v = tid; v < vmax / 4; v += bd) s4[v] = make_int4(0, 0, 0, 0);
        }
        __syncthreads();
        for (int k = tid; k < n; k += bd) atomicAdd(&sh[in[k]], 1);
        __syncthreads();

        const int chunk = (vmax + bd - 1) / bd;
        const int c0 = min(tid * chunk, vmax);
        const int c1 = min(c0 + chunk, vmax);
        int cnt = 0;
        for (int v = c0; v < c1; v++) cnt += (sh[v] != 0);

        // exclusive scan across 1024 threads
        int incl = cnt;
        #pragma unroll
        for (int off = 1; off < 32; off <<= 1) {
            int t = __shfl_up_sync(0xFFFFFFFFu, incl, off);
            if (lane >= off) incl += t;
        }
        if (lane == 31) wsum[wid] = incl;
        __syncthreads();
        if (wid == 0) {
            int s = wsum[lane];
            #pragma unroll
            for (int off = 1; off < 32; off <<= 1) {
                int t = __shfl_up_sync(0xFFFFFFFFu, s, off);
                if (lane >= off) s += t;
            }
            wsum[lane] = s;
        }
        __syncthreads();
        int excl = incl - cnt + (wid > 0 ? wsum[wid - 1] : 0);

        for (int v = c0; v < c1; v++) {
            int c = sh[v];
            if (c) { outv[excl] = v; outw[excl] = (float)c; excl++; }
        }
        if (tid == bd - 1) d_nu[b] = excl;

        // signal completion (after ALL threads' stores)
        __syncthreads();
        if (tid == 0) {
            __threadfence();
            atomicAdd(&d_sd, 1);
        }
        return;
    }

    // ================= prep block =================
    if (tid == 0) {
        while (atomicAdd(&d_sd, 0) < 4) __nanosleep(64);   // wait for all 4 sorts
    }
    __syncthreads();   // all threads see the fence-ordered sort outputs

    const int t = (b - 4) * 1024 + tid;
    const int nu_1 = d_nu[0], nu_2 = d_nu[1], nu_g = d_nu[2], nu_r = d_nu[3];
    float ng2 = 0.0f, nr2 = 0.0f;

    if (t < MRv) {
        if (t < nu_r) {
            int v = d_sr[t];
            float p0, p1, p2; softmax3(Cr[3*v], Cr[3*v+1], Cr[3*v+2], p0, p1, p2);
            d_pr[t] = make_float4(p0, p1, p2, br[v]);
            nr2 = d_wr[t] * (p0*p0 + p1*p1 + p2*p2);
        }
    } else if (t < MRv + MGv) {
        int j = t - MRv;
        if (j < nu_g) {
            int v = d_sg[j];
            float p0, p1, p2; softmax3(Cg[3*v], Cg[3*v+1], Cg[3*v+2], p0, p1, p2);
            d_pg[j] = make_float4(p0, p1, p2, bg[v]);
            ng2 = d_wg[j] * (p0*p0 + p1*p1 + p2*p2);
        }
    } else if (t < MRv + MGv + M1v) {
        int i = t - MRv - MGv;
        if (i < nu_1) {
            int v = d_s1[i];
            float p0, p1, p2; softmax3(C1[3*v], C1[3*v+1], C1[3*v+2], p0, p1, p2);
            float q0 = p0*Ai[0] + p1*Ai[3] + p2*Ai[6];
            float q1 = p0*Ai[1] + p1*Ai[4] + p2*Ai[7];
            float q2 = p0*Ai[2] + p1*Ai[5] + p2*Ai[8];
            d_q1[i] = make_float4(q0, q1, q2, b1[v]);
        }
    } else if (t < MRv + MGv + M1v + M2v) {
        int i = t - MRv - MGv - M1v;
        if (i < nu_2) {
            int v = d_s2[i];
            float p0, p1, p2; softmax3(C2[3*v], C2[3*v+1], C2[3*v+2], p0, p1, p2);
            float q0 = p0*Ai[0] + p1*Ai[3] + p2*Ai[6];
            float q1 = p0*Ai[1] + p1*Ai[4] + p2*Ai[7];
            float q2 = p0*Ai[2] + p1*Ai[5] + p2*Ai[8];
            d_q2[i] = make_float4(q0, q1, q2, b2[v]);
        }
    }

    // block-reduce norm partials -> 2 atomics/block
    ng2 = warp_sum(ng2); nr2 = warp_sum(nr2);
    if (lane == 0) { red_a[wid] = ng2; red_b[wid] = nr2; }
    __syncthreads();
    if (wid == 0) {
        float xg = red_a[lane], xr = red_b[lane];
        xg = warp_sum(xg); xr = warp_sum(xr);
        if (lane == 0) {
            if (xg != 0.0f) atomicAdd(&d_acc[3], (double)xg);
            if (xr != 0.0f) atomicAdd(&d_acc[4], (double)xr);
        }
    }

    // last prep block resets the counters for the next graph replay
    __syncthreads();
    if (tid == 0) {
        int prev = atomicAdd(&d_pd, 1);
        if (prev == NPREP - 1) { d_sd = 0; d_pd = 0; __threadfence(); }
    }
}

// ---------------- loss kernel: static grid, single wave, 2 j-cols/thread --------
__global__ void __launch_bounds__(256)
loss_kernel(const float* __restrict__ G, const float* __restrict__ R,
            const float* __restrict__ A) {
    __shared__ float4 sq[64];
    __shared__ int    soff[64];
    __shared__ float  sw[64];
    __shared__ float  red[8];
    const int tid = threadIdx.x, lane = tid & 31, wid = tid >> 5;
    int b = blockIdx.x;

    const int nu1 = d_nu[0], nu2 = d_nu[1], nug = d_nu[2], nur = d_nu[3];
    float part = 0.0f;
    int accIdx;

    if (b < NB3) {
        // ---- loss3: S += w_i w_j * (pg_i . pr_j) * A[sg_i, sr_j] ----
        accIdx = 2;
        const int bx = b % GXJ, by = b / GXJ;
        const int i0 = by * 64, jb = bx * 512;
        if (i0 < nug && jb < nur) {
            if (tid < 64) {
                int i = i0 + tid;
                if (i < nug) {
                    float4 p = d_pg[i]; float w = d_wg[i];
                    sq[tid] = make_float4(p.x * w, p.y * w, p.z * w, 0.0f);
                    soff[tid] = d_sg[i] * RD;
                }
            }
            __syncthreads();
            const int j0 = jb + tid, j1 = j0 + 256;
            const bool v0 = j0 < nur, v1 = j1 < nur;
            const int   c0 = v0 ? d_sr[j0] : 0;
            const int   c1 = v1 ? d_sr[j1] : 0;
            const float4 p0 = v0 ? d_pr[j0] : make_float4(0,0,0,0);
            const float4 p1 = v1 ? d_pr[j1] : make_float4(0,0,0,0);
            const float w0 = v0 ? d_wr[j0] : 0.0f;
            const float w1 = v1 ? d_wr[j1] : 0.0f;
            float a0=0,a1=0,a2=0, e0=0,e1=0,e2=0;
            const int ilim = min(64, nug - i0);
            #pragma unroll 8
            for (int i = 0; i < ilim; i++) {
                int off = soff[i];
                float av = __ldg(A + off + c0);
                float bv = __ldg(A + off + c1);
                float4 g = sq[i];
                a0 = fmaf(av, g.x, a0); a1 = fmaf(av, g.y, a1); a2 = fmaf(av, g.z, a2);
                e0 = fmaf(bv, g.x, e0); e1 = fmaf(bv, g.y, e1); e2 = fmaf(bv, g.z, e2);
            }
            part = (a0*p0.x + a1*p0.y + a2*p0.z) * w0
                 + (e0*p1.x + e1*p1.y + e2*p1.z) * w1;
        }
    } else {
        // ---- weighted squared-residual losses ----
        const float* X; int ld, TI, bx, by, nu_i, nu_j;
        const int *si, *sj; const float *wiA, *wjA; const float4 *qA, *pA;
        int u = b - NB3;
        if (u < NB2) {          // loss2 over R
            X = R; ld = RD; TI = 64; bx = u % GXJ; by = u / GXJ;
            nu_i = nu2; nu_j = nur; accIdx = 1;
            si = d_s2; wiA = d_w2; qA = d_q2; sj = d_sr; wjA = d_wr; pA = d_pr;
        } else {                // loss1 over G
            u -= NB2;
            X = G; ld = GD; TI = 32; bx = u % GX1; by = u / GX1;
            nu_i = nu1; nu_j = nug; accIdx = 0;
            si = d_s1; wiA = d_w1; qA = d_q1; sj = d_sg; wjA = d_wg; pA = d_pg;
        }
        const int i0 = by * TI, jb = bx * 512;
        if (i0 < nu_i && jb < nu_j) {
            if (tid < TI) {
                int i = i0 + tid;
                if (i < nu_i) { sq[tid] = qA[i]; soff[tid] = si[i] * ld; sw[tid] = wiA[i]; }
            }
            __syncthreads();
            const int j0 = jb + tid, j1 = j0 + 256;
            const bool v0 = j0 < nu_j, v1 = j1 < nu_j;
            const int   c0 = v0 ? sj[j0] : 0;
            const int   c1 = v1 ? sj[j1] : 0;
            const float4 p0 = v0 ? pA[j0] : make_float4(0,0,0,0);
            const float4 p1 = v1 ? pA[j1] : make_float4(0,0,0,0);
            const float w0 = v0 ? wjA[j0] : 0.0f;
            const float w1 = v1 ? wjA[j1] : 0.0f;
            float accA = 0.0f, accB = 0.0f;
            const int ilim = min(TI, nu_i - i0);
            #pragma unroll 8
            for (int i = 0; i < ilim; i++) {
                float4 qi = sq[i];
                int off = soff[i];
                float wi = sw[i];
                float gA = __ldg(X + off + c0);
                float gB = __ldg(X + off + c1);
                float rA = gA - fmaf(qi.x, p0.x, fmaf(qi.y, p0.y, qi.z * p0.z))
                              - p0.w - qi.w;
                float rB = gB - fmaf(qi.x, p1.x, fmaf(qi.y, p1.y, qi.z * p1.z))
                              - p1.w - qi.w;
                accA = fmaf(wi * rA, rA, accA);
                accB = fmaf(wi * rB, rB, accB);
            }
            part = accA * w0 + accB * w1;
        }
    }

    // warp-shuffle block reduction -> one double atomic per block
    part = warp_sum(part);
    if (lane == 0) red[wid] = part;
    __syncthreads();
    if (wid == 0) {
        float v = (lane < 8) ? red[lane] : 0.0f;
        #pragma unroll
        for (int off = 4; off > 0; off >>= 1)
            v += __shfl_down_sync(0xFFFFFFFFu, v, off);
        if (lane == 0) atomicAdd(&d_acc[accIdx], (double)v);
    }
}

// ---------------- finalize ----------------
__global__ void finalize_kernel(float* __restrict__ out) {
    double t1 = 1000.0 * (d_acc[0] / (double)((long long)M1v * MGv));
    double t2 = 1000.0 * (d_acc[1] / (double)((long long)M2v * MRv));
    double t3 = 100.0  * (-d_acc[2] / (sqrt(d_acc[3]) * sqrt(d_acc[4])));
    out[0] = (float)(t1 + t2 + t3);
    out[1] = (float)t1;
    out[2] = (float)t2;
    out[3] = (float)t3;
    out[4] = 0.0f;   // ALPHA[3] == 0 -> exactly 0
}

// ---------------- launch ----------------
extern "C" void kernel_launch(void* const* d_in, const int* in_sizes, int n_in,
                              void* d_out, int out_size) {
    const float* G  = (const float*)d_in[0];
    const float* R  = (const float*)d_in[1];
    const float* A  = (const float*)d_in[2];
    const float* C1 = (const float*)d_in[3];
    const float* C2 = (const float*)d_in[4];
    const float* Cg = (const float*)d_in[5];
    const float* Cr = (const float*)d_in[6];
    const float* Ai = (const float*)d_in[7];
    const float* bg = (const float*)d_in[8];
    const float* br = (const float*)d_in[9];
    const float* b1 = (const float*)d_in[10];
    const float* b2 = (const float*)d_in[11];
    const int* m1 = (const int*)d_in[12];
    const int* m2 = (const int*)d_in[13];
    const int* mg = (const int*)d_in[14];
    const int* mr = (const int*)d_in[15];
    float* out = (float*)d_out;

    // largest histogram (R_DIM = 20000 ints = 80 KB) exceeds default 48 KB
    cudaFuncSetAttribute(sort_prep_kernel,
                         cudaFuncAttributeMaxDynamicSharedMemorySize,
                         RD * (int)sizeof(int));

    sort_prep_kernel<<<NSP, 1024, RD * sizeof(int)>>>(m1, m2, mg, mr,
                                                      C1, C2, Cg, Cr, Ai,
                                                      bg, br, b1, b2);
    loss_kernel<<<NBT, 256>>>(G, R, A);
    finalize_kernel<<<1, 32>>>(out);
}

// round 16
// speedup vs baseline: 1.0381x; 1.0381x over previous
#include <cuda_runtime.h>
#include <math.h>

// Problem constants
#define N1v 4000
#define N2v 4000
#define GD  8000
#define RD  20000
#define M1v 1200
#define M2v 1200
#define MGv 2400
#define MRv 6000

// Loss tiling: 2 j-columns per thread, 512-wide j-tiles -> 874 blocks (single wave)
#define GXJ 12            // ceil(MRv/512)
#define GY3 38            // ceil(MGv/64)
#define NB3 (GXJ*GY3)     // 456
#define GY2 19            // ceil(M2v/64)
#define NB2 (GXJ*GY2)     // 228
#define GX1 5             // ceil(MGv/512)
#define GY1 38            // ceil(M1v/32)
#define NB1 (GX1*GY1)     // 190
#define NBT (NB3+NB2+NB1) // 874

// ---------------- device scratch (no allocation allowed) ----------------
__device__ int    d_s1[M1v], d_s2[M2v], d_sg[MGv], d_sr[MRv];
__device__ float  d_w1[M1v], d_w2[M2v], d_wg[MGv], d_wr[MRv];
__device__ float4 d_q1[M1v], d_q2[M2v], d_pg[MGv], d_pr[MRv];
__device__ int    d_nu[4];      // unique counts: [m1, m2, mg, mr]
// 0: loss1, 1: loss2, 2: S (trace), 3: ||Pg||^2, 4: ||Pr||^2
__device__ double d_acc[5];

// ---------------- helpers ----------------
__device__ __forceinline__ void softmax3(float a, float b, float c,
                                         float& p0, float& p1, float& p2) {
    float m  = fmaxf(a, fmaxf(b, c));
    float e0 = __expf(a - m), e1 = __expf(b - m), e2 = __expf(c - m);
    float inv = 1.0f / (e0 + e1 + e2);
    p0 = e0 * inv; p1 = e1 * inv; p2 = e2 * inv;
}

__device__ __forceinline__ float warp_sum(float v) {
    #pragma unroll
    for (int off = 16; off > 0; off >>= 1)
        v += __shfl_down_sync(0xFFFFFFFFu, v, off);
    return v;
}

// ---------------- counting sort + dedup (4 concurrent blocks, smem histogram) ----
// Sorting/dedup is exact: all sums are permutation-invariant and every per-index
// quantity depends only on the mask VALUE; duplicates -> multiplicity weights.
// Sorted unique column values give quasi-coalesced gathers in the loss kernel.
__global__ void sort_kernel(const int* __restrict__ m1, const int* __restrict__ m2,
                            const int* __restrict__ mg, const int* __restrict__ mr) {
    extern __shared__ int sh[];           // per-block histogram (up to RD ints)
    __shared__ int wsum[32];
    const int which = blockIdx.x;
    const int tid = threadIdx.x, bd = blockDim.x;   // bd == 1024
    const int lane = tid & 31, wid = tid >> 5;

    const int* in; int n, vmax; int* outv; float* outw;
    if      (which == 0) { in = m1; n = M1v; vmax = N1v; outv = d_s1; outw = d_w1; }
    else if (which == 1) { in = m2; n = M2v; vmax = N2v; outv = d_s2; outw = d_w2; }
    else if (which == 2) { in = mg; n = MGv; vmax = GD;  outv = d_sg; outw = d_wg; }
    else                 { in = mr; n = MRv; vmax = RD;  outv = d_sr; outw = d_wr; }

    if (which == 0 && tid < 5) d_acc[tid] = 0.0;   // reset accumulators each replay

    // zero histogram (int4-vectorized; vmax % 4 == 0, extern smem is 16B aligned)
    {
        int4* s4 = reinterpret_cast<int4*>(sh);
        for (int v = tid; v < vmax / 4; v += bd) s4[v] = make_int4(0, 0, 0, 0);
    }
    __syncthreads();
    for (int k = tid; k < n; k += bd) atomicAdd(&sh[in[k]], 1);
    __syncthreads();

    const int chunk = (vmax + bd - 1) / bd;
    const int c0 = min(tid * chunk, vmax);
    const int c1 = min(c0 + chunk, vmax);
    int cnt = 0;                                   // # unique values in my chunk
    for (int v = c0; v < c1; v++) cnt += (sh[v] != 0);

    // exclusive scan of cnt across 1024 threads via warp shuffles
    int incl = cnt;
    #pragma unroll
    for (int off = 1; off < 32; off <<= 1) {
        int t = __shfl_up_sync(0xFFFFFFFFu, incl, off);
        if (lane >= off) incl += t;
    }
    if (lane == 31) wsum[wid] = incl;
    __syncthreads();
    if (wid == 0) {
        int s = wsum[lane];
        #pragma unroll
        for (int off = 1; off < 32; off <<= 1) {
            int t = __shfl_up_sync(0xFFFFFFFFu, s, off);
            if (lane >= off) s += t;
        }
        wsum[lane] = s;
    }
    __syncthreads();
    int excl = incl - cnt + (wid > 0 ? wsum[wid - 1] : 0);

    for (int v = c0; v < c1; v++) {
        int c = sh[v];
        if (c) { outv[excl] = v; outw[excl] = (float)c; excl++; }
    }
    if (tid == bd - 1) d_nu[which] = excl;
}

// ---------------- prep: softmax tables, Q = P@Ai, biases, weighted norms --------
__global__ void prep_kernel(const float* __restrict__ C1, const float* __restrict__ C2,
                            const float* __restrict__ Cg, const float* __restrict__ Cr,
                            const float* __restrict__ Ai, const float* __restrict__ bg,
                            const float* __restrict__ br, const float* __restrict__ b1,
                            const float* __restrict__ b2) {
    const int t = blockIdx.x * blockDim.x + threadIdx.x;
    const int nu_1 = d_nu[0], nu_2 = d_nu[1], nu_g = d_nu[2], nu_r = d_nu[3];
    float ng2 = 0.0f, nr2 = 0.0f;

    if (t < MRv) {
        if (t < nu_r) {
            int v = d_sr[t];
            float p0, p1, p2; softmax3(Cr[3*v], Cr[3*v+1], Cr[3*v+2], p0, p1, p2);
            d_pr[t] = make_float4(p0, p1, p2, br[v]);
            nr2 = d_wr[t] * (p0*p0 + p1*p1 + p2*p2);
        }
    } else if (t < MRv + MGv) {
        int j = t - MRv;
        if (j < nu_g) {
            int v = d_sg[j];
            float p0, p1, p2; softmax3(Cg[3*v], Cg[3*v+1], Cg[3*v+2], p0, p1, p2);
            d_pg[j] = make_float4(p0, p1, p2, bg[v]);
            ng2 = d_wg[j] * (p0*p0 + p1*p1 + p2*p2);
        }
    } else if (t < MRv + MGv + M1v) {
        int i = t - MRv - MGv;
        if (i < nu_1) {
            int v = d_s1[i];
            float p0, p1, p2; softmax3(C1[3*v], C1[3*v+1], C1[3*v+2], p0, p1, p2);
            float q0 = p0*Ai[0] + p1*Ai[3] + p2*Ai[6];
            float q1 = p0*Ai[1] + p1*Ai[4] + p2*Ai[7];
            float q2 = p0*Ai[2] + p1*Ai[5] + p2*Ai[8];
            d_q1[i] = make_float4(q0, q1, q2, b1[v]);
        }
    } else if (t < MRv + MGv + M1v + M2v) {
        int i = t - MRv - MGv - M1v;
        if (i < nu_2) {
            int v = d_s2[i];
            float p0, p1, p2; softmax3(C2[3*v], C2[3*v+1], C2[3*v+2], p0, p1, p2);
            float q0 = p0*Ai[0] + p1*Ai[3] + p2*Ai[6];
            float q1 = p0*Ai[1] + p1*Ai[4] + p2*Ai[7];
            float q2 = p0*Ai[2] + p1*Ai[5] + p2*Ai[8];
            d_q2[i] = make_float4(q0, q1, q2, b2[v]);
        }
    }

    __shared__ float rg[256], rr[256];
    const int tid = threadIdx.x;
    rg[tid] = ng2; rr[tid] = nr2;
    __syncthreads();
    for (int s = 128; s > 0; s >>= 1) {
        if (tid < s) { rg[tid] += rg[tid + s]; rr[tid] += rr[tid + s]; }
        __syncthreads();
    }
    if (tid == 0) {
        if (rg[0] != 0.0f) atomicAdd(&d_acc[3], (double)rg[0]);
        if (rr[0] != 0.0f) atomicAdd(&d_acc[4], (double)rr[0]);
    }
}

// ---------------- loss kernel: static grid, single wave, 2 j-cols/thread --------
// Matrix loads use __ldcs (streaming, evict-first): A/G/R elements are strictly
// read-once, so they shouldn't displace the hot per-j tables from L1.
__global__ void __launch_bounds__(256)
loss_kernel(const float* __restrict__ G, const float* __restrict__ R,
            const float* __restrict__ A) {
    __shared__ float4 sq[64];
    __shared__ int    soff[64];
    __shared__ float  sw[64];
    __shared__ float  red[8];
    const int tid = threadIdx.x, lane = tid & 31, wid = tid >> 5;
    int b = blockIdx.x;

    const int nu1 = d_nu[0], nu2 = d_nu[1], nug = d_nu[2], nur = d_nu[3];
    float part = 0.0f;
    int accIdx;

    if (b < NB3) {
        // ---- loss3: S += w_i w_j * (pg_i . pr_j) * A[sg_i, sr_j] ----
        accIdx = 2;
        const int bx = b % GXJ, by = b / GXJ;
        const int i0 = by * 64, jb = bx * 512;
        if (i0 < nug && jb < nur) {
            if (tid < 64) {
                int i = i0 + tid;
                if (i < nug) {
                    float4 p = d_pg[i]; float w = d_wg[i];
                    sq[tid] = make_float4(p.x * w, p.y * w, p.z * w, 0.0f);
                    soff[tid] = d_sg[i] * RD;
                }
            }
            __syncthreads();
            const int j0 = jb + tid, j1 = j0 + 256;
            const bool v0 = j0 < nur, v1 = j1 < nur;
            const int   c0 = v0 ? d_sr[j0] : 0;
            const int   c1 = v1 ? d_sr[j1] : 0;
            const float4 p0 = v0 ? d_pr[j0] : make_float4(0,0,0,0);
            const float4 p1 = v1 ? d_pr[j1] : make_float4(0,0,0,0);
            const float w0 = v0 ? d_wr[j0] : 0.0f;
            const float w1 = v1 ? d_wr[j1] : 0.0f;
            float a0=0,a1=0,a2=0, e0=0,e1=0,e2=0;
            const int ilim = min(64, nug - i0);
            #pragma unroll 8
            for (int i = 0; i < ilim; i++) {
                int off = soff[i];
                float av = __ldcs(A + off + c0);
                float bv = __ldcs(A + off + c1);
                float4 g = sq[i];
                a0 = fmaf(av, g.x, a0); a1 = fmaf(av, g.y, a1); a2 = fmaf(av, g.z, a2);
                e0 = fmaf(bv, g.x, e0); e1 = fmaf(bv, g.y, e1); e2 = fmaf(bv, g.z, e2);
            }
            part = (a0*p0.x + a1*p0.y + a2*p0.z) * w0
                 + (e0*p1.x + e1*p1.y + e2*p1.z) * w1;
        }
    } else {
        // ---- weighted squared-residual losses ----
        const float* X; int ld, TI, bx, by, nu_i, nu_j;
        const int *si, *sj; const float *wiA, *wjA; const float4 *qA, *pA;
        int u = b - NB3;
        if (u < NB2) {          // loss2 over R
            X = R; ld = RD; TI = 64; bx = u % GXJ; by = u / GXJ;
            nu_i = nu2; nu_j = nur; accIdx = 1;
            si = d_s2; wiA = d_w2; qA = d_q2; sj = d_sr; wjA = d_wr; pA = d_pr;
        } else {                // loss1 over G
            u -= NB2;
            X = G; ld = GD; TI = 32; bx = u % GX1; by = u / GX1;
            nu_i = nu1; nu_j = nug; accIdx = 0;
            si = d_s1; wiA = d_w1; qA = d_q1; sj = d_sg; wjA = d_wg; pA = d_pg;
        }
        const int i0 = by * TI, jb = bx * 512;
        if (i0 < nu_i && jb < nu_j) {
            if (tid < TI) {
                int i = i0 + tid;
                if (i < nu_i) { sq[tid] = qA[i]; soff[tid] = si[i] * ld; sw[tid] = wiA[i]; }
            }
            __syncthreads();
            const int j0 = jb + tid, j1 = j0 + 256;
            const bool v0 = j0 < nu_j, v1 = j1 < nu_j;
            const int   c0 = v0 ? sj[j0] : 0;
            const int   c1 = v1 ? sj[j1] : 0;
            const float4 p0 = v0 ? pA[j0] : make_float4(0,0,0,0);
            const float4 p1 = v1 ? pA[j1] : make_float4(0,0,0,0);
            const float w0 = v0 ? wjA[j0] : 0.0f;
            const float w1 = v1 ? wjA[j1] : 0.0f;
            float accA = 0.0f, accB = 0.0f;
            const int ilim = min(TI, nu_i - i0);
            #pragma unroll 8
            for (int i = 0; i < ilim; i++) {
                float4 qi = sq[i];
                int off = soff[i];
                float wi = sw[i];
                float gA = __ldcs(X + off + c0);
                float gB = __ldcs(X + off + c1);
                float rA = gA - fmaf(qi.x, p0.x, fmaf(qi.y, p0.y, qi.z * p0.z))
                              - p0.w - qi.w;
                float rB = gB - fmaf(qi.x, p1.x, fmaf(qi.y, p1.y, qi.z * p1.z))
                              - p1.w - qi.w;
                accA = fmaf(wi * rA, rA, accA);
                accB = fmaf(wi * rB, rB, accB);
            }
            part = accA * w0 + accB * w1;
        }
    }

    // warp-shuffle block reduction -> one double atomic per block
    part = warp_sum(part);
    if (lane == 0) red[wid] = part;
    __syncthreads();
    if (wid == 0) {
        float v = (lane < 8) ? red[lane] : 0.0f;
        #pragma unroll
        for (int off = 4; off > 0; off >>= 1)
            v += __shfl_down_sync(0xFFFFFFFFu, v, off);
        if (lane == 0) atomicAdd(&d_acc[accIdx], (double)v);
    }
}

// ---------------- finalize ----------------
__global__ void finalize_kernel(float* __restrict__ out) {
    double t1 = 1000.0 * (d_acc[0] / (double)((long long)M1v * MGv));
    double t2 = 1000.0 * (d_acc[1] / (double)((long long)M2v * MRv));
    double t3 = 100.0  * (-d_acc[2] / (sqrt(d_acc[3]) * sqrt(d_acc[4])));
    out[0] = (float)(t1 + t2 + t3);
    out[1] = (float)t1;
    out[2] = (float)t2;
    out[3] = (float)t3;
    out[4] = 0.0f;   // ALPHA[3] == 0 -> exactly 0
}

// ---------------- launch ----------------
extern "C" void kernel_launch(void* const* d_in, const int* in_sizes, int n_in,
                              void* d_out, int out_size) {
    const float* G  = (const float*)d_in[0];
    const float* R  = (const float*)d_in[1];
    const float* A  = (const float*)d_in[2];
    const float* C1 = (const float*)d_in[3];
    const float* C2 = (const float*)d_in[4];
    const float* Cg = (const float*)d_in[5];
    const float* Cr = (const float*)d_in[6];
    const float* Ai = (const float*)d_in[7];
    const float* bg = (const float*)d_in[8];
    const float* br = (const float*)d_in[9];
    const float* b1 = (const float*)d_in[10];
    const float* b2 = (const float*)d_in[11];
    const int* m1 = (const int*)d_in[12];
    const int* m2 = (const int*)d_in[13];
    const int* mg = (const int*)d_in[14];
    const int* mr = (const int*)d_in[15];
    float* out = (float*)d_out;

    // largest histogram (R_DIM = 20000 ints = 80 KB) exceeds default 48 KB
    cudaFuncSetAttribute(sort_kernel,
                         cudaFuncAttributeMaxDynamicSharedMemorySize,
                         RD * (int)sizeof(int));

    sort_kernel<<<4, 1024, RD * sizeof(int)>>>(m1, m2, mg, mr);

    {
        int total = MRv + MGv + M1v + M2v;          // 10800
        prep_kernel<<<(total + 255) / 256, 256>>>(C1, C2, Cg, Cr, Ai, bg, br, b1, b2);
    }

    loss_kernel<<<NBT, 256>>>(G, R, A);
    finalize_kernel<<<1, 32>>>(out);
}